// round 2
// baseline (speedup 1.0000x reference)
#include <cuda_runtime.h>

#define NPTS 2048
#define NB   8
#define KNN  20
#define EPSV 1e-6f
#define TILE 16
#define BPB  (NPTS / TILE)   // 128 blocks per batch in layer kernels

// ---------------- device scratch (no allocation allowed) ----------------
__device__ int    g_idx[NB * NPTS * KNN];
__device__ float4 g_net0[NB * NPTS * 64];    // [b][n][ch]  (x,y,z,pad)
__device__ float4 g_net1[NB * NPTS * 128];
__device__ float4 g_net2[NB * NPTS * 128];

__device__ float g_Wn_pos[64 * 3];
__device__ float g_Wn1T[64 * 128];    // [i][o] transposed, row-normalized
__device__ float g_D1T [64 * 128];
__device__ float g_Wn2T[128 * 128];   // first 128 cols of normalized W2, transposed
__device__ float g_D2T [128 * 128];
__device__ float g_Wn3T[128 * 128];
__device__ float g_D3T [128 * 128];
__device__ float g_Wn2F[128 * 256];   // full normalized W2 row-major (for bias part)
__device__ float g_Wn3F[128 * 256];

__device__ float g_part1[NB * BPB * 384];    // deterministic partial sums
__device__ float g_part2[NB * BPB * 384];
__device__ float g_part3[NB * BPB * 384];
__device__ float g_biasP2[NB * 384];
__device__ float g_biasD2[NB * 384];
__device__ float g_biasP3[NB * 384];
__device__ float g_biasD3[NB * 384];

// ---------------- weight prep: normalize rows + transpose ----------------
// one block per weight matrix, threadIdx.x = output row
__global__ void __launch_bounds__(128)
prep_kernel(const float* __restrict__ Wpos,
            const float* __restrict__ W1,
            const float* __restrict__ W2,
            const float* __restrict__ W3,
            const float* __restrict__ D1,
            const float* __restrict__ D2,
            const float* __restrict__ D3) {
    int which = blockIdx.x;
    int rr = threadIdx.x;
    if (which == 0) {
        if (rr < 64) {
            const float* s = Wpos + rr * 3;
            float sum = s[0] + s[1] + s[2];
            for (int i = 0; i < 3; i++) g_Wn_pos[rr * 3 + i] = s[i] / sum;
        }
    } else if (which == 1) {
        const float* s = W1 + rr * 64;
        float sum = 0.f;
#pragma unroll 1
        for (int i = 0; i < 64; i++) sum += s[i];
        float inv = 1.f / sum;
#pragma unroll 1
        for (int i = 0; i < 64; i++) g_Wn1T[i * 128 + rr] = s[i] * inv;
    } else if (which == 2) {
        const float* s = W2 + rr * 256;
        float sum = 0.f;
#pragma unroll 1
        for (int i = 0; i < 256; i++) sum += s[i];
        float inv = 1.f / sum;
#pragma unroll 1
        for (int i = 0; i < 256; i++) {
            float v = s[i] * inv;
            g_Wn2F[rr * 256 + i] = v;
            if (i < 128) g_Wn2T[i * 128 + rr] = v;
        }
    } else if (which == 3) {
        const float* s = W3 + rr * 256;
        float sum = 0.f;
#pragma unroll 1
        for (int i = 0; i < 256; i++) sum += s[i];
        float inv = 1.f / sum;
#pragma unroll 1
        for (int i = 0; i < 256; i++) {
            float v = s[i] * inv;
            g_Wn3F[rr * 256 + i] = v;
            if (i < 128) g_Wn3T[i * 128 + rr] = v;
        }
    } else if (which == 4) {
#pragma unroll 1
        for (int i = 0; i < 64; i++) g_D1T[i * 128 + rr] = D1[rr * 64 + i];
    } else if (which == 5) {
#pragma unroll 1
        for (int i = 0; i < 128; i++) g_D2T[i * 128 + rr] = D2[rr * 256 + i];
    } else {
#pragma unroll 1
        for (int i = 0; i < 128; i++) g_D3T[i * 128 + rr] = D3[rr * 256 + i];
    }
}

// ---------------- kNN: top-20 by pairwise = 2*dot - |xi|^2 - |xj|^2 ----------------
__global__ void __launch_bounds__(128)
knn_kernel(const float* __restrict__ pc) {
    __shared__ float4 sq[NPTS];
    int b = blockIdx.y;
    const float* pb = pc + b * NPTS * 3;
    for (int m = threadIdx.x; m < NPTS; m += blockDim.x) {
        float x = pb[m * 3 + 0], y = pb[m * 3 + 1], z = pb[m * 3 + 2];
        sq[m] = make_float4(x, y, z, x * x + y * y + z * z);
    }
    __syncthreads();
    int n = blockIdx.x * blockDim.x + threadIdx.x;
    float4 c = sq[n];
    float best[KNN];
    int   bi[KNN];
#pragma unroll
    for (int j = 0; j < KNN; j++) { best[j] = -1e30f; bi[j] = 0; }
#pragma unroll 1
    for (int m = 0; m < NPTS; m++) {
        float4 q = sq[m];
        float d = 2.f * (c.x * q.x + c.y * q.y + c.z * q.z) - c.w - q.w;
        if (d > best[KNN - 1]) {
            // stable insertion: strict compare => ties keep earlier index (jax top_k)
            int j = KNN - 1;
            while (j > 0 && best[j - 1] < d) {
                best[j] = best[j - 1]; bi[j] = bi[j - 1]; j--;
            }
            best[j] = d; bi[j] = m;
        }
    }
    int* op = g_idx + (b * NPTS + n) * KNN;
    for (int j = 0; j < KNN; j++) op[j] = bi[j];
}

// ---------------- edge features + pos layer + mean over k -> net0 ----------------
// channels: x0 = nbr-ctr, x1 = ctr, x2 = cross(nbr, ctr)
__global__ void __launch_bounds__(128)
edge_pos_kernel(const float* __restrict__ pc,
                const float* __restrict__ Dpos) {
    __shared__ float4 nbr[2][KNN];
    __shared__ float wsh[64 * 3], dsh[64 * 3];
    int half = threadIdx.x >> 6;
    int o = threadIdx.x & 63;
    int pt = blockIdx.x * 2 + half;
    int b = pt / NPTS;
    int n = pt % NPTS;
    for (int t = threadIdx.x; t < 192; t += 128) {
        wsh[t] = g_Wn_pos[t];
        dsh[t] = Dpos[t];
    }
    if (o < KNN) {
        int m = g_idx[(b * NPTS + n) * KNN + o];
        const float* q = pc + (b * NPTS + m) * 3;
        nbr[half][o] = make_float4(q[0], q[1], q[2], 0.f);
    }
    __syncthreads();
    const float* cp = pc + (b * NPTS + n) * 3;
    float cx = cp[0], cy = cp[1], cz = cp[2];
    float w0 = wsh[o * 3 + 0], w1 = wsh[o * 3 + 1], w2 = wsh[o * 3 + 2];
    float d0 = dsh[o * 3 + 0], d1 = dsh[o * 3 + 1], d2 = dsh[o * 3 + 2];
    float a0 = 0.f, a1 = 0.f, a2 = 0.f;
#pragma unroll 4
    for (int kk = 0; kk < KNN; kk++) {
        float4 q = nbr[half][kk];
        float e0 = q.x - cx, e1 = q.y - cy, e2 = q.z - cz;
        float r0 = q.y * cz - q.z * cy;
        float r1 = q.z * cx - q.x * cz;
        float r2 = q.x * cy - q.y * cx;
        float p0 = w0 * e0 + w1 * cx + w2 * r0;
        float p1 = w0 * e1 + w1 * cy + w2 * r1;
        float p2 = w0 * e2 + w1 * cz + w2 * r2;
        float q0 = d0 * e0 + d1 * cx + d2 * r0;
        float q1 = d0 * e1 + d1 * cy + d2 * r1;
        float q2 = d0 * e2 + d1 * cz + d2 * r2;
        float dot = p0 * q0 + p1 * q1 + p2 * q2;
        if (dot < 0.f) {
            float dns = q0 * q0 + q1 * q1 + q2 * q2;
            float tt = dot / (dns + EPSV);
            p0 -= tt * q0; p1 -= tt * q1; p2 -= tt * q2;
        }
        a0 += p0; a1 += p1; a2 += p2;
    }
    const float inv = 1.f / (float)KNN;
    g_net0[pt * 64 + o] = make_float4(a0 * inv, a1 * inv, a2 * inv, 0.f);
}

// ---------------- generic VNT layer: out = lrelu(Wn@x [+bias], D@x [+bias]) ----------------
template <int IN_CH, bool STORE, bool BIAS>
__global__ void __launch_bounds__(256)
layer_kernel(const float4* __restrict__ in, const float* __restrict__ WnT,
             const float* __restrict__ DT,
             const float* __restrict__ biasP, const float* __restrict__ biasD,
             float4* __restrict__ out, float* __restrict__ part) {
    extern __shared__ float smem[];
    float*  WsT = smem;                       // [IN_CH][128]
    float*  DsT = WsT + IN_CH * 128;
    float4* xs  = (float4*)(DsT + IN_CH * 128);  // [TILE][IN_CH]

    int b   = blockIdx.x / BPB;
    int blk = blockIdx.x % BPB;
    int p0  = blk * TILE;
    int tid = threadIdx.x;

    for (int t = tid; t < IN_CH * 128; t += 256) {
        WsT[t] = WnT[t];
        DsT[t] = DT[t];
    }
    const float4* inp = in + ((long)b * NPTS + p0) * IN_CH;
    for (int t = tid; t < TILE * IN_CH; t += 256) xs[t] = inp[t];
    __syncthreads();

    int o = tid & 127;
    int g = tid >> 7;

    float bP0 = 0.f, bP1 = 0.f, bP2 = 0.f, bD0 = 0.f, bD1 = 0.f, bD2 = 0.f;
    if (BIAS) {
        bP0 = biasP[b * 384 + o * 3 + 0];
        bP1 = biasP[b * 384 + o * 3 + 1];
        bP2 = biasP[b * 384 + o * 3 + 2];
        bD0 = biasD[b * 384 + o * 3 + 0];
        bD1 = biasD[b * 384 + o * 3 + 1];
        bD2 = biasD[b * 384 + o * 3 + 2];
    }

    float aP[8][3], aD[8][3];
#pragma unroll
    for (int p = 0; p < 8; p++) {
        aP[p][0] = bP0; aP[p][1] = bP1; aP[p][2] = bP2;
        aD[p][0] = bD0; aD[p][1] = bD1; aD[p][2] = bD2;
    }

    const float4* xg = xs + g * 8 * IN_CH;
#pragma unroll 2
    for (int i = 0; i < IN_CH; ++i) {
        float w  = WsT[i * 128 + o];
        float dd = DsT[i * 128 + o];
#pragma unroll
        for (int p = 0; p < 8; ++p) {
            float4 x = xg[p * IN_CH + i];
            aP[p][0] += w * x.x;  aP[p][1] += w * x.y;  aP[p][2] += w * x.z;
            aD[p][0] += dd * x.x; aD[p][1] += dd * x.y; aD[p][2] += dd * x.z;
        }
    }

    float s0 = 0.f, s1 = 0.f, s2 = 0.f;
#pragma unroll
    for (int p = 0; p < 8; p++) {
        float q0 = aP[p][0], q1 = aP[p][1], q2 = aP[p][2];
        float dot = q0 * aD[p][0] + q1 * aD[p][1] + q2 * aD[p][2];
        if (dot < 0.f) {
            float dns = aD[p][0] * aD[p][0] + aD[p][1] * aD[p][1] + aD[p][2] * aD[p][2];
            float tt = dot / (dns + EPSV);
            q0 -= tt * aD[p][0]; q1 -= tt * aD[p][1]; q2 -= tt * aD[p][2];
        }
        if (STORE)
            out[((long)b * NPTS + p0 + g * 8 + p) * 128 + o] = make_float4(q0, q1, q2, 0.f);
        s0 += q0; s1 += q1; s2 += q2;
    }

    // deterministic block-partial sum (over the 16 points of this block)
    __syncthreads();
    float* red = smem;  // reuse (>= 768 floats available)
    red[tid * 3 + 0] = s0; red[tid * 3 + 1] = s1; red[tid * 3 + 2] = s2;
    __syncthreads();
    if (tid < 128) {
        float t0 = red[tid * 3 + 0] + red[(tid + 128) * 3 + 0];
        float t1 = red[tid * 3 + 1] + red[(tid + 128) * 3 + 1];
        float t2 = red[tid * 3 + 2] + red[(tid + 128) * 3 + 2];
        float* dst = part + ((long)(b * BPB + blk)) * 384 + tid * 3;
        dst[0] = t0; dst[1] = t1; dst[2] = t2;
    }
}

// ---------------- bias from pooled mean: bias = W[:,128:] @ mean, D[:,128:] @ mean ----------------
__global__ void __launch_bounds__(128)
bias_kernel(const float* __restrict__ part,
            const float* __restrict__ WnF,   // [128][256] normalized
            const float* __restrict__ Draw,  // [128][256] raw
            float* __restrict__ biasP, float* __restrict__ biasD) {
    __shared__ float mean[384];
    int b = blockIdx.x;
    int tid = threadIdx.x;  // 128
    for (int t = tid; t < 384; t += 128) {
        float s = 0.f;
#pragma unroll 1
        for (int blk = 0; blk < BPB; blk++) s += part[((long)(b * BPB + blk)) * 384 + t];
        mean[t] = s * (1.f / (float)NPTS);
    }
    __syncthreads();
    int o = tid;
    float p0 = 0.f, p1 = 0.f, p2 = 0.f, d0 = 0.f, d1 = 0.f, d2 = 0.f;
#pragma unroll 1
    for (int i = 0; i < 128; i++) {
        float w  = WnF[o * 256 + 128 + i];
        float dd = Draw[o * 256 + 128 + i];
        float m0 = mean[i * 3 + 0], m1 = mean[i * 3 + 1], m2 = mean[i * 3 + 2];
        p0 += w * m0;  p1 += w * m1;  p2 += w * m2;
        d0 += dd * m0; d1 += dd * m1; d2 += dd * m2;
    }
    biasP[b * 384 + o * 3 + 0] = p0;
    biasP[b * 384 + o * 3 + 1] = p1;
    biasP[b * 384 + o * 3 + 2] = p2;
    biasD[b * 384 + o * 3 + 0] = d0;
    biasD[b * 384 + o * 3 + 1] = d1;
    biasD[b * 384 + o * 3 + 2] = d2;
}

// ---------------- final mean over N -> output [B,384] ----------------
__global__ void __launch_bounds__(384)
final_kernel(const float* __restrict__ part, float* __restrict__ outp) {
    int b = blockIdx.x;
    int t = threadIdx.x;  // 384
    float s = 0.f;
#pragma unroll 1
    for (int blk = 0; blk < BPB; blk++) s += part[((long)(b * BPB + blk)) * 384 + t];
    outp[b * 384 + t] = s * (1.f / (float)NPTS);
}

// ---------------- launch ----------------
extern "C" void kernel_launch(void* const* d_in, const int* in_sizes, int n_in,
                              void* d_out, int out_size) {
    const float* pc   = (const float*)d_in[0];
    const float* Wpos = (const float*)d_in[1];
    const float* Dpos = (const float*)d_in[2];
    const float* W1   = (const float*)d_in[3];
    const float* D1   = (const float*)d_in[4];
    const float* W2   = (const float*)d_in[5];
    const float* D2   = (const float*)d_in[6];
    const float* W3   = (const float*)d_in[7];
    const float* D3   = (const float*)d_in[8];
    float* outp = (float*)d_out;

    int smem1 = (64 * 128 * 2) * 4 + TILE * 64 * 16;     //  81920 B
    int smem2 = (128 * 128 * 2) * 4 + TILE * 128 * 16;   // 163840 B
    cudaFuncSetAttribute(layer_kernel<64, true, false>,
                         cudaFuncAttributeMaxDynamicSharedMemorySize, smem1);
    cudaFuncSetAttribute(layer_kernel<128, true, true>,
                         cudaFuncAttributeMaxDynamicSharedMemorySize, smem2);
    cudaFuncSetAttribute(layer_kernel<128, false, true>,
                         cudaFuncAttributeMaxDynamicSharedMemorySize, smem2);

    void *net0p, *net1p, *net2p;
    void *wn1t, *d1t, *wn2t, *d2t, *wn3t, *d3t, *wn2f, *wn3f;
    void *part1, *part2, *part3, *bp2, *bd2, *bp3, *bd3;
    cudaGetSymbolAddress(&net0p, g_net0);
    cudaGetSymbolAddress(&net1p, g_net1);
    cudaGetSymbolAddress(&net2p, g_net2);
    cudaGetSymbolAddress(&wn1t, g_Wn1T);
    cudaGetSymbolAddress(&d1t,  g_D1T);
    cudaGetSymbolAddress(&wn2t, g_Wn2T);
    cudaGetSymbolAddress(&d2t,  g_D2T);
    cudaGetSymbolAddress(&wn3t, g_Wn3T);
    cudaGetSymbolAddress(&d3t,  g_D3T);
    cudaGetSymbolAddress(&wn2f, g_Wn2F);
    cudaGetSymbolAddress(&wn3f, g_Wn3F);
    cudaGetSymbolAddress(&part1, g_part1);
    cudaGetSymbolAddress(&part2, g_part2);
    cudaGetSymbolAddress(&part3, g_part3);
    cudaGetSymbolAddress(&bp2, g_biasP2);
    cudaGetSymbolAddress(&bd2, g_biasD2);
    cudaGetSymbolAddress(&bp3, g_biasP3);
    cudaGetSymbolAddress(&bd3, g_biasD3);

    prep_kernel<<<7, 128>>>(Wpos, W1, W2, W3, D1, D2, D3);
    knn_kernel<<<dim3(NPTS / 128, NB), 128>>>(pc);
    edge_pos_kernel<<<NB * NPTS / 2, 128>>>(pc, Dpos);

    layer_kernel<64, true, false><<<NB * BPB, 256, smem1>>>(
        (const float4*)net0p, (const float*)wn1t, (const float*)d1t,
        nullptr, nullptr, (float4*)net1p, (float*)part1);

    bias_kernel<<<NB, 128>>>((const float*)part1, (const float*)wn2f, D2,
                             (float*)bp2, (float*)bd2);

    layer_kernel<128, true, true><<<NB * BPB, 256, smem2>>>(
        (const float4*)net1p, (const float*)wn2t, (const float*)d2t,
        (const float*)bp2, (const float*)bd2, (float4*)net2p, (float*)part2);

    bias_kernel<<<NB, 128>>>((const float*)part2, (const float*)wn3f, D3,
                             (float*)bp3, (float*)bd3);

    layer_kernel<128, false, true><<<NB * BPB, 256, smem2>>>(
        (const float4*)net2p, (const float*)wn3t, (const float*)d3t,
        (const float*)bp3, (const float*)bd3, nullptr, (float*)part3);

    final_kernel<<<NB, 384>>>((const float*)part3, outp);
}

// round 3
// speedup vs baseline: 1.6599x; 1.6599x over previous
#include <cuda_runtime.h>

#define NPTS 2048
#define NB   8
#define KNN  20
#define EPSV 1e-6f
#define TILE 16
#define BPB  (NPTS / TILE)   // 128 tiles per batch
#define TPB  8               // tiles per block in layer kernels
#define LBPB (BPB / TPB)     // 16 layer blocks per batch

// ---------------- device scratch (no allocation allowed) ----------------
__device__ int    g_idx[NB * NPTS * KNN];
__device__ float4 g_net0[NB * NPTS * 64];    // [b][n][ch]  (x,y,z,pad)
__device__ float4 g_net1[NB * NPTS * 128];
__device__ float4 g_net2[NB * NPTS * 128];

__device__ float g_Wn_pos[64 * 3];
__device__ float g_Wn1T[64 * 128];    // [i][o] transposed, row-normalized
__device__ float g_D1T [64 * 128];
__device__ float g_Wn2T[128 * 128];   // first 128 cols of normalized W2, transposed
__device__ float g_D2T [128 * 128];
__device__ float g_Wn3T[128 * 128];
__device__ float g_D3T [128 * 128];
__device__ float g_Wn2F[128 * 256];   // full normalized W2 row-major (for bias part)
__device__ float g_Wn3F[128 * 256];

__device__ float g_part1[NB * BPB * 384];    // deterministic partial sums
__device__ float g_part2[NB * BPB * 384];
__device__ float g_part3[NB * BPB * 384];
__device__ float g_biasP2[NB * 384];
__device__ float g_biasD2[NB * 384];
__device__ float g_biasP3[NB * 384];
__device__ float g_biasD3[NB * 384];

// ---------------- weight prep: normalize rows + transpose ----------------
__global__ void __launch_bounds__(128)
prep_kernel(const float* __restrict__ Wpos,
            const float* __restrict__ W1,
            const float* __restrict__ W2,
            const float* __restrict__ W3,
            const float* __restrict__ D1,
            const float* __restrict__ D2,
            const float* __restrict__ D3) {
    int which = blockIdx.x;
    int rr = threadIdx.x;
    if (which == 0) {
        if (rr < 64) {
            const float* s = Wpos + rr * 3;
            float sum = s[0] + s[1] + s[2];
            for (int i = 0; i < 3; i++) g_Wn_pos[rr * 3 + i] = s[i] / sum;
        }
    } else if (which == 1) {
        const float* s = W1 + rr * 64;
        float sum = 0.f;
#pragma unroll 1
        for (int i = 0; i < 64; i++) sum += s[i];
        float inv = 1.f / sum;
#pragma unroll 1
        for (int i = 0; i < 64; i++) g_Wn1T[i * 128 + rr] = s[i] * inv;
    } else if (which == 2) {
        const float* s = W2 + rr * 256;
        float sum = 0.f;
#pragma unroll 1
        for (int i = 0; i < 256; i++) sum += s[i];
        float inv = 1.f / sum;
#pragma unroll 1
        for (int i = 0; i < 256; i++) {
            float v = s[i] * inv;
            g_Wn2F[rr * 256 + i] = v;
            if (i < 128) g_Wn2T[i * 128 + rr] = v;
        }
    } else if (which == 3) {
        const float* s = W3 + rr * 256;
        float sum = 0.f;
#pragma unroll 1
        for (int i = 0; i < 256; i++) sum += s[i];
        float inv = 1.f / sum;
#pragma unroll 1
        for (int i = 0; i < 256; i++) {
            float v = s[i] * inv;
            g_Wn3F[rr * 256 + i] = v;
            if (i < 128) g_Wn3T[i * 128 + rr] = v;
        }
    } else if (which == 4) {
#pragma unroll 1
        for (int i = 0; i < 64; i++) g_D1T[i * 128 + rr] = D1[rr * 64 + i];
    } else if (which == 5) {
#pragma unroll 1
        for (int i = 0; i < 128; i++) g_D2T[i * 128 + rr] = D2[rr * 256 + i];
    } else {
#pragma unroll 1
        for (int i = 0; i < 128; i++) g_D3T[i * 128 + rr] = D3[rr * 256 + i];
    }
}

// ---------------- kNN: warp-per-query, warp-distributed top-20 ----------------
// Lane i of each warp holds the i-th largest (value, index); tau = 20th value.
// A candidate is processed only if it beats tau (expected ~113 of 2048).
__global__ void __launch_bounds__(256)
knn_kernel(const float* __restrict__ pc) {
    __shared__ float4 sq[NPTS];
    int b = blockIdx.y;
    const float* pb = pc + b * NPTS * 3;
    for (int m = threadIdx.x; m < NPTS; m += 256) {
        float x = pb[m * 3 + 0], y = pb[m * 3 + 1], z = pb[m * 3 + 2];
        sq[m] = make_float4(x, y, z, x * x + y * y + z * z);
    }
    __syncthreads();

    int wid  = threadIdx.x >> 5;
    int lane = threadIdx.x & 31;
    int n = blockIdx.x * 8 + wid;
    float4 c = sq[n];

    float val = -3.4e38f;
    int   idx = 0;
    float tau = -3.4e38f;

#pragma unroll 1
    for (int r = 0; r < NPTS / 32; r++) {
        int m = r * 32 + lane;
        float4 q = sq[m];
        float d = 2.f * (c.x * q.x + c.y * q.y + c.z * q.z) - c.w - q.w;
        unsigned mask = __ballot_sync(0xffffffffu, d > tau);
        while (mask) {
            int src = __ffs(mask) - 1;
            mask &= mask - 1;
            float dc = __shfl_sync(0xffffffffu, d, src);
            if (dc > tau) {   // warp-uniform (dc, tau identical across lanes)
                int mc = r * 32 + src;
                float vup = __shfl_up_sync(0xffffffffu, val, 1);
                int   iup = __shfl_up_sync(0xffffffffu, idx, 1);
                bool cw = dc > val;            // strict: ties keep earlier index
                float t  = cw ? dc : val;
                int   ti = cw ? mc : idx;
                bool up = (lane > 0) && (vup < t);
                val = up ? vup : t;
                idx = up ? iup : ti;
                tau = __shfl_sync(0xffffffffu, val, KNN - 1);
            }
        }
    }
    if (lane < KNN) g_idx[(b * NPTS + n) * KNN + lane] = idx;
}

// ---------------- edge features + pos layer + mean over k -> net0 ----------------
__global__ void __launch_bounds__(128)
edge_pos_kernel(const float* __restrict__ pc,
                const float* __restrict__ Dpos) {
    __shared__ float4 nbr[2][KNN];
    __shared__ float wsh[64 * 3], dsh[64 * 3];
    int half = threadIdx.x >> 6;
    int o = threadIdx.x & 63;
    int pt = blockIdx.x * 2 + half;
    int b = pt / NPTS;
    int n = pt % NPTS;
    for (int t = threadIdx.x; t < 192; t += 128) {
        wsh[t] = g_Wn_pos[t];
        dsh[t] = Dpos[t];
    }
    if (o < KNN) {
        int m = g_idx[(b * NPTS + n) * KNN + o];
        const float* q = pc + (b * NPTS + m) * 3;
        nbr[half][o] = make_float4(q[0], q[1], q[2], 0.f);
    }
    __syncthreads();
    const float* cp = pc + (b * NPTS + n) * 3;
    float cx = cp[0], cy = cp[1], cz = cp[2];
    float w0 = wsh[o * 3 + 0], w1 = wsh[o * 3 + 1], w2 = wsh[o * 3 + 2];
    float d0 = dsh[o * 3 + 0], d1 = dsh[o * 3 + 1], d2 = dsh[o * 3 + 2];
    float a0 = 0.f, a1 = 0.f, a2 = 0.f;
#pragma unroll 4
    for (int kk = 0; kk < KNN; kk++) {
        float4 q = nbr[half][kk];
        float e0 = q.x - cx, e1 = q.y - cy, e2 = q.z - cz;
        float r0 = q.y * cz - q.z * cy;
        float r1 = q.z * cx - q.x * cz;
        float r2 = q.x * cy - q.y * cx;
        float p0 = w0 * e0 + w1 * cx + w2 * r0;
        float p1 = w0 * e1 + w1 * cy + w2 * r1;
        float p2 = w0 * e2 + w1 * cz + w2 * r2;
        float q0 = d0 * e0 + d1 * cx + d2 * r0;
        float q1 = d0 * e1 + d1 * cy + d2 * r1;
        float q2 = d0 * e2 + d1 * cz + d2 * r2;
        float dot = p0 * q0 + p1 * q1 + p2 * q2;
        if (dot < 0.f) {
            float dns = q0 * q0 + q1 * q1 + q2 * q2;
            float tt = dot / (dns + EPSV);
            p0 -= tt * q0; p1 -= tt * q1; p2 -= tt * q2;
        }
        a0 += p0; a1 += p1; a2 += p2;
    }
    const float inv = 1.f / (float)KNN;
    g_net0[pt * 64 + o] = make_float4(a0 * inv, a1 * inv, a2 * inv, 0.f);
}

// ---------------- VNT layer: persistent weights, loop over TPB tiles ----------------
template <int IN_CH, bool STORE, bool BIAS>
__global__ void __launch_bounds__(256)
layer_kernel(const float4* __restrict__ in, const float* __restrict__ WnT,
             const float* __restrict__ DT,
             const float* __restrict__ biasP, const float* __restrict__ biasD,
             float4* __restrict__ out, float* __restrict__ part) {
    extern __shared__ float smem[];
    float*  WsT = smem;                          // [IN_CH][128]
    float*  DsT = WsT + IN_CH * 128;
    float4* xs  = (float4*)(DsT + IN_CH * 128);  // [TILE][IN_CH]
    float*  red = (float*)(xs + TILE * IN_CH);   // [256*3]

    int b    = blockIdx.x / LBPB;
    int blk0 = (blockIdx.x % LBPB) * TPB;
    int tid  = threadIdx.x;

    for (int t = tid; t < IN_CH * 128; t += 256) {
        WsT[t] = WnT[t];
        DsT[t] = DT[t];
    }

    int o = tid & 127;
    int g = tid >> 7;

    float bP0 = 0.f, bP1 = 0.f, bP2 = 0.f, bD0 = 0.f, bD1 = 0.f, bD2 = 0.f;
    if (BIAS) {
        bP0 = biasP[b * 384 + o * 3 + 0];
        bP1 = biasP[b * 384 + o * 3 + 1];
        bP2 = biasP[b * 384 + o * 3 + 2];
        bD0 = biasD[b * 384 + o * 3 + 0];
        bD1 = biasD[b * 384 + o * 3 + 1];
        bD2 = biasD[b * 384 + o * 3 + 2];
    }
    __syncthreads();

#pragma unroll 1
    for (int t = 0; t < TPB; t++) {
        int blk = blk0 + t;
        int p0  = blk * TILE;

        const float4* inp = in + ((long)b * NPTS + p0) * IN_CH;
        for (int tt = tid; tt < TILE * IN_CH; tt += 256) xs[tt] = inp[tt];
        __syncthreads();

        float aP[8][3], aD[8][3];
#pragma unroll
        for (int p = 0; p < 8; p++) {
            aP[p][0] = bP0; aP[p][1] = bP1; aP[p][2] = bP2;
            aD[p][0] = bD0; aD[p][1] = bD1; aD[p][2] = bD2;
        }

        const float4* xg = xs + g * 8 * IN_CH;
#pragma unroll 2
        for (int i = 0; i < IN_CH; ++i) {
            float w  = WsT[i * 128 + o];
            float dd = DsT[i * 128 + o];
#pragma unroll
            for (int p = 0; p < 8; ++p) {
                float4 x = xg[p * IN_CH + i];
                aP[p][0] += w * x.x;  aP[p][1] += w * x.y;  aP[p][2] += w * x.z;
                aD[p][0] += dd * x.x; aD[p][1] += dd * x.y; aD[p][2] += dd * x.z;
            }
        }

        float s0 = 0.f, s1 = 0.f, s2 = 0.f;
#pragma unroll
        for (int p = 0; p < 8; p++) {
            float q0 = aP[p][0], q1 = aP[p][1], q2 = aP[p][2];
            float dot = q0 * aD[p][0] + q1 * aD[p][1] + q2 * aD[p][2];
            if (dot < 0.f) {
                float dns = aD[p][0] * aD[p][0] + aD[p][1] * aD[p][1] + aD[p][2] * aD[p][2];
                float tt2 = dot / (dns + EPSV);
                q0 -= tt2 * aD[p][0]; q1 -= tt2 * aD[p][1]; q2 -= tt2 * aD[p][2];
            }
            if (STORE)
                out[((long)b * NPTS + p0 + g * 8 + p) * 128 + o] = make_float4(q0, q1, q2, 0.f);
            s0 += q0; s1 += q1; s2 += q2;
        }

        red[tid * 3 + 0] = s0; red[tid * 3 + 1] = s1; red[tid * 3 + 2] = s2;
        __syncthreads();
        if (tid < 128) {
            float t0 = red[tid * 3 + 0] + red[(tid + 128) * 3 + 0];
            float t1 = red[tid * 3 + 1] + red[(tid + 128) * 3 + 1];
            float t2 = red[tid * 3 + 2] + red[(tid + 128) * 3 + 2];
            float* dst = part + ((long)(b * BPB + blk)) * 384 + tid * 3;
            dst[0] = t0; dst[1] = t1; dst[2] = t2;
        }
        // next iteration's xs-load sync doubles as the red-read barrier
    }
}

// ---------------- bias from pooled mean ----------------
__global__ void __launch_bounds__(128)
bias_kernel(const float* __restrict__ part,
            const float* __restrict__ WnF,   // [128][256] normalized
            const float* __restrict__ Draw,  // [128][256] raw
            float* __restrict__ biasP, float* __restrict__ biasD) {
    __shared__ float mean[384];
    int b = blockIdx.x;
    int tid = threadIdx.x;  // 128
    for (int t = tid; t < 384; t += 128) {
        float s = 0.f;
#pragma unroll 1
        for (int blk = 0; blk < BPB; blk++) s += part[((long)(b * BPB + blk)) * 384 + t];
        mean[t] = s * (1.f / (float)NPTS);
    }
    __syncthreads();
    int o = tid;
    float p0 = 0.f, p1 = 0.f, p2 = 0.f, d0 = 0.f, d1 = 0.f, d2 = 0.f;
#pragma unroll 1
    for (int i = 0; i < 128; i++) {
        float w  = WnF[o * 256 + 128 + i];
        float dd = Draw[o * 256 + 128 + i];
        float m0 = mean[i * 3 + 0], m1 = mean[i * 3 + 1], m2 = mean[i * 3 + 2];
        p0 += w * m0;  p1 += w * m1;  p2 += w * m2;
        d0 += dd * m0; d1 += dd * m1; d2 += dd * m2;
    }
    biasP[b * 384 + o * 3 + 0] = p0;
    biasP[b * 384 + o * 3 + 1] = p1;
    biasP[b * 384 + o * 3 + 2] = p2;
    biasD[b * 384 + o * 3 + 0] = d0;
    biasD[b * 384 + o * 3 + 1] = d1;
    biasD[b * 384 + o * 3 + 2] = d2;
}

// ---------------- final mean over N -> output [B,384] ----------------
__global__ void __launch_bounds__(384)
final_kernel(const float* __restrict__ part, float* __restrict__ outp) {
    int b = blockIdx.x;
    int t = threadIdx.x;  // 384
    float s = 0.f;
#pragma unroll 1
    for (int blk = 0; blk < BPB; blk++) s += part[((long)(b * BPB + blk)) * 384 + t];
    outp[b * 384 + t] = s * (1.f / (float)NPTS);
}

// ---------------- launch ----------------
extern "C" void kernel_launch(void* const* d_in, const int* in_sizes, int n_in,
                              void* d_out, int out_size) {
    const float* pc   = (const float*)d_in[0];
    const float* Wpos = (const float*)d_in[1];
    const float* Dpos = (const float*)d_in[2];
    const float* W1   = (const float*)d_in[3];
    const float* D1   = (const float*)d_in[4];
    const float* W2   = (const float*)d_in[5];
    const float* D2   = (const float*)d_in[6];
    const float* W3   = (const float*)d_in[7];
    const float* D3   = (const float*)d_in[8];
    float* outp = (float*)d_out;

    int smem1 = (64 * 128 * 2) * 4 + TILE * 64 * 16 + 256 * 3 * 4;    //  84992 B
    int smem2 = (128 * 128 * 2) * 4 + TILE * 128 * 16 + 256 * 3 * 4;  // 166912 B
    cudaFuncSetAttribute(layer_kernel<64, true, false>,
                         cudaFuncAttributeMaxDynamicSharedMemorySize, smem1);
    cudaFuncSetAttribute(layer_kernel<128, true, true>,
                         cudaFuncAttributeMaxDynamicSharedMemorySize, smem2);
    cudaFuncSetAttribute(layer_kernel<128, false, true>,
                         cudaFuncAttributeMaxDynamicSharedMemorySize, smem2);

    void *net0p, *net1p, *net2p;
    void *wn1t, *d1t, *wn2t, *d2t, *wn3t, *d3t, *wn2f, *wn3f;
    void *part1, *part2, *part3, *bp2, *bd2, *bp3, *bd3;
    cudaGetSymbolAddress(&net0p, g_net0);
    cudaGetSymbolAddress(&net1p, g_net1);
    cudaGetSymbolAddress(&net2p, g_net2);
    cudaGetSymbolAddress(&wn1t, g_Wn1T);
    cudaGetSymbolAddress(&d1t,  g_D1T);
    cudaGetSymbolAddress(&wn2t, g_Wn2T);
    cudaGetSymbolAddress(&d2t,  g_D2T);
    cudaGetSymbolAddress(&wn3t, g_Wn3T);
    cudaGetSymbolAddress(&d3t,  g_D3T);
    cudaGetSymbolAddress(&wn2f, g_Wn2F);
    cudaGetSymbolAddress(&wn3f, g_Wn3F);
    cudaGetSymbolAddress(&part1, g_part1);
    cudaGetSymbolAddress(&part2, g_part2);
    cudaGetSymbolAddress(&part3, g_part3);
    cudaGetSymbolAddress(&bp2, g_biasP2);
    cudaGetSymbolAddress(&bd2, g_biasD2);
    cudaGetSymbolAddress(&bp3, g_biasP3);
    cudaGetSymbolAddress(&bd3, g_biasD3);

    prep_kernel<<<7, 128>>>(Wpos, W1, W2, W3, D1, D2, D3);
    knn_kernel<<<dim3(NPTS / 8, NB), 256>>>(pc);
    edge_pos_kernel<<<NB * NPTS / 2, 128>>>(pc, Dpos);

    layer_kernel<64, true, false><<<NB * LBPB, 256, smem1>>>(
        (const float4*)net0p, (const float*)wn1t, (const float*)d1t,
        nullptr, nullptr, (float4*)net1p, (float*)part1);

    bias_kernel<<<NB, 128>>>((const float*)part1, (const float*)wn2f, D2,
                             (float*)bp2, (float*)bd2);

    layer_kernel<128, true, true><<<NB * LBPB, 256, smem2>>>(
        (const float4*)net1p, (const float*)wn2t, (const float*)d2t,
        (const float*)bp2, (const float*)bd2, (float4*)net2p, (float*)part2);

    bias_kernel<<<NB, 128>>>((const float*)part2, (const float*)wn3f, D3,
                             (float*)bp3, (float*)bd3);

    layer_kernel<128, false, true><<<NB * LBPB, 256, smem2>>>(
        (const float4*)net2p, (const float*)wn3t, (const float*)d3t,
        (const float*)bp3, (const float*)bd3, nullptr, (float*)part3);

    final_kernel<<<NB, 384>>>((const float*)part3, outp);
}

// round 4
// speedup vs baseline: 2.8809x; 1.7356x over previous
#include <cuda_runtime.h>

#define NPTS 2048
#define NB   8
#define KNN  20
#define EPSV 1e-6f
#define TILE 16
#define BPB  (NPTS / TILE)   // 128 tiles per batch
#define TPB  8               // tiles per block in layer kernels
#define LBPB (BPB / TPB)     // 16 layer blocks per batch

typedef unsigned long long u64t;

__device__ __forceinline__ u64t fma2(u64t a, u64t b, u64t c) {
    u64t d;
    asm("fma.rn.f32x2 %0, %1, %2, %3;" : "=l"(d) : "l"(a), "l"(b), "l"(c));
    return d;
}
__device__ __forceinline__ u64t pack2(float lo, float hi) {
    u64t d;
    asm("mov.b64 %0, {%1, %2};" : "=l"(d) : "f"(lo), "f"(hi));
    return d;
}
__device__ __forceinline__ void unpack2(u64t v, float& lo, float& hi) {
    asm("mov.b64 {%0, %1}, %2;" : "=f"(lo), "=f"(hi) : "l"(v));
}

// ---------------- device scratch ----------------
// feature buffers in component-major tile layout:
//   buf[ ((b*BPB + blk)*CH + ch) * 48 + comp*16 + p ]   (p = point within 16-pt tile)
__device__ int   g_idx[NB * NPTS * KNN];
__device__ float g_net0[NB * BPB * 64 * 48];
__device__ float g_net1[NB * BPB * 128 * 48];
__device__ float g_net2[NB * BPB * 128 * 48];

__device__ float g_Wn_pos[64 * 3];
__device__ float g_Wn1T[64 * 128];    // [i][o] transposed, row-normalized
__device__ float g_D1T [64 * 128];
__device__ float g_Wn2T[128 * 128];   // first 128 cols of normalized W2, transposed
__device__ float g_D2T [128 * 128];
__device__ float g_Wn3T[128 * 128];
__device__ float g_D3T [128 * 128];
__device__ float g_Wn2F[128 * 256];   // full normalized W2 row-major (for bias part)
__device__ float g_Wn3F[128 * 256];

__device__ float g_part1[NB * BPB * 384];
__device__ float g_part2[NB * BPB * 384];
__device__ float g_part3[NB * BPB * 384];
__device__ float g_biasP2[NB * 384];
__device__ float g_biasD2[NB * 384];
__device__ float g_biasP3[NB * 384];
__device__ float g_biasD3[NB * 384];

// ---------------- prep A: row-normalize W matrices (block per row) ----------------
// blockIdx 0: Wpos (64 rows, trivial). 1..128: W1. 129..256: W2. 257..384: W3.
__global__ void __launch_bounds__(128)
prep_norm_kernel(const float* __restrict__ Wpos, const float* __restrict__ W1,
                 const float* __restrict__ W2,   const float* __restrict__ W3) {
    __shared__ float sr[128];
    int tid = threadIdx.x;
    int bx = blockIdx.x;
    if (bx == 0) {
        if (tid < 64) {
            const float* s = Wpos + tid * 3;
            float sum = s[0] + s[1] + s[2];
            for (int i = 0; i < 3; i++) g_Wn_pos[tid * 3 + i] = s[i] / sum;
        }
        return;
    }
    if (bx <= 128) {
        int r = bx - 1;
        float v = (tid < 64) ? W1[r * 64 + tid] : 0.f;
        sr[tid] = v;
        __syncthreads();
        for (int s = 64; s > 0; s >>= 1) {
            if (tid < s) sr[tid] += sr[tid + s];
            __syncthreads();
        }
        float inv = 1.f / sr[0];
        if (tid < 64) g_Wn1T[tid * 128 + r] = v * inv;
        return;
    }
    const float* W = (bx <= 256) ? W2 : W3;
    float* WT = (bx <= 256) ? g_Wn2T : g_Wn3T;
    float* WF = (bx <= 256) ? g_Wn2F : g_Wn3F;
    int r = (bx <= 256) ? (bx - 129) : (bx - 257);
    float v0 = W[r * 256 + tid];
    float v1 = W[r * 256 + tid + 128];
    sr[tid] = v0 + v1;
    __syncthreads();
    for (int s = 64; s > 0; s >>= 1) {
        if (tid < s) sr[tid] += sr[tid + s];
        __syncthreads();
    }
    float inv = 1.f / sr[0];
    float n0 = v0 * inv, n1 = v1 * inv;
    WF[r * 256 + tid] = n0;
    WF[r * 256 + tid + 128] = n1;
    WT[tid * 128 + r] = n0;
}

// ---------------- prep B: transpose D matrices (grid-stride) ----------------
__global__ void __launch_bounds__(256)
prep_transpose_kernel(const float* __restrict__ D1, const float* __restrict__ D2,
                      const float* __restrict__ D3) {
    int idx = blockIdx.x * 256 + threadIdx.x;
    if (idx < 8192) {                       // D1: [128][64] -> D1T [64][128]
        int i = idx >> 7, rr = idx & 127;
        g_D1T[i * 128 + rr] = D1[rr * 64 + i];
    } else if (idx < 8192 + 16384) {        // D2 first 128 cols
        int t = idx - 8192;
        int i = t >> 7, rr = t & 127;
        g_D2T[i * 128 + rr] = D2[rr * 256 + i];
    } else if (idx < 8192 + 32768) {        // D3 first 128 cols
        int t = idx - 8192 - 16384;
        int i = t >> 7, rr = t & 127;
        g_D3T[i * 128 + rr] = D3[rr * 256 + i];
    }
}

// ---------------- kNN: warp-per-query, warp-distributed top-20 ----------------
__global__ void __launch_bounds__(256)
knn_kernel(const float* __restrict__ pc) {
    __shared__ float4 sq[NPTS];
    int b = blockIdx.y;
    const float* pb = pc + b * NPTS * 3;
    for (int m = threadIdx.x; m < NPTS; m += 256) {
        float x = pb[m * 3 + 0], y = pb[m * 3 + 1], z = pb[m * 3 + 2];
        sq[m] = make_float4(x, y, z, x * x + y * y + z * z);
    }
    __syncthreads();

    int wid  = threadIdx.x >> 5;
    int lane = threadIdx.x & 31;
    int n = blockIdx.x * 8 + wid;
    float4 c = sq[n];

    float val = -3.4e38f;
    int   idx = 0;
    float tau = -3.4e38f;

#pragma unroll 1
    for (int r = 0; r < NPTS / 32; r++) {
        int m = r * 32 + lane;
        float4 q = sq[m];
        float d = 2.f * (c.x * q.x + c.y * q.y + c.z * q.z) - c.w - q.w;
        unsigned mask = __ballot_sync(0xffffffffu, d > tau);
        while (mask) {
            int src = __ffs(mask) - 1;
            mask &= mask - 1;
            float dc = __shfl_sync(0xffffffffu, d, src);
            if (dc > tau) {
                int mc = r * 32 + src;
                float vup = __shfl_up_sync(0xffffffffu, val, 1);
                int   iup = __shfl_up_sync(0xffffffffu, idx, 1);
                bool cw = dc > val;
                float t  = cw ? dc : val;
                int   ti = cw ? mc : idx;
                bool up = (lane > 0) && (vup < t);
                val = up ? vup : t;
                idx = up ? iup : ti;
                tau = __shfl_sync(0xffffffffu, val, KNN - 1);
            }
        }
    }
    if (lane < KNN) g_idx[(b * NPTS + n) * KNN + lane] = idx;
}

// ---------------- edge features + pos layer + mean over k -> net0 (comp-major) ----------------
__global__ void __launch_bounds__(128)
edge_pos_kernel(const float* __restrict__ pc,
                const float* __restrict__ Dpos) {
    __shared__ float4 nbr[2][KNN];
    __shared__ float wsh[64 * 3], dsh[64 * 3];
    int half = threadIdx.x >> 6;
    int o = threadIdx.x & 63;
    int pt = blockIdx.x * 2 + half;
    int b = pt / NPTS;
    int n = pt % NPTS;
    for (int t = threadIdx.x; t < 192; t += 128) {
        wsh[t] = g_Wn_pos[t];
        dsh[t] = Dpos[t];
    }
    if (o < KNN) {
        int m = g_idx[(b * NPTS + n) * KNN + o];
        const float* q = pc + (b * NPTS + m) * 3;
        nbr[half][o] = make_float4(q[0], q[1], q[2], 0.f);
    }
    __syncthreads();
    const float* cp = pc + (b * NPTS + n) * 3;
    float cx = cp[0], cy = cp[1], cz = cp[2];
    float w0 = wsh[o * 3 + 0], w1 = wsh[o * 3 + 1], w2 = wsh[o * 3 + 2];
    float d0 = dsh[o * 3 + 0], d1 = dsh[o * 3 + 1], d2 = dsh[o * 3 + 2];
    float a0 = 0.f, a1 = 0.f, a2 = 0.f;
#pragma unroll 4
    for (int kk = 0; kk < KNN; kk++) {
        float4 q = nbr[half][kk];
        float e0 = q.x - cx, e1 = q.y - cy, e2 = q.z - cz;
        float r0 = q.y * cz - q.z * cy;
        float r1 = q.z * cx - q.x * cz;
        float r2 = q.x * cy - q.y * cx;
        float p0 = w0 * e0 + w1 * cx + w2 * r0;
        float p1 = w0 * e1 + w1 * cy + w2 * r1;
        float p2 = w0 * e2 + w1 * cz + w2 * r2;
        float q0 = d0 * e0 + d1 * cx + d2 * r0;
        float q1 = d0 * e1 + d1 * cy + d2 * r1;
        float q2 = d0 * e2 + d1 * cz + d2 * r2;
        float dot = p0 * q0 + p1 * q1 + p2 * q2;
        if (dot < 0.f) {
            float dns = q0 * q0 + q1 * q1 + q2 * q2;
            float tt = dot / (dns + EPSV);
            p0 -= tt * q0; p1 -= tt * q1; p2 -= tt * q2;
        }
        a0 += p0; a1 += p1; a2 += p2;
    }
    const float inv = 1.f / (float)KNN;
    int blk = n >> 4, pp = n & 15;
    float* dst = g_net0 + ((long)(b * BPB + blk) * 64 + o) * 48;
    dst[0 * 16 + pp] = a0 * inv;
    dst[1 * 16 + pp] = a1 * inv;
    dst[2 * 16 + pp] = a2 * inv;
}

// ---------------- VNT layer: packed f32x2, persistent weights ----------------
// in/out layout: [(b*BPB+blk)*CH + ch]*48 + comp*16 + p
template <int IN_CH, bool STORE, bool BIAS>
__global__ void __launch_bounds__(512)
layer_kernel(const float* __restrict__ in, const float* __restrict__ WnT,
             const float* __restrict__ DT,
             const float* __restrict__ biasP, const float* __restrict__ biasD,
             float* __restrict__ out, float* __restrict__ part) {
    extern __shared__ float smem[];
    float* WsT = smem;                          // [IN_CH][128]
    float* DsT = WsT + IN_CH * 128;
    float* xs  = DsT + IN_CH * 128;             // [IN_CH][3][16]
    float* red = xs + IN_CH * 48;               // [512*3]

    int b    = blockIdx.x / LBPB;
    int blk0 = (blockIdx.x % LBPB) * TPB;
    int tid  = threadIdx.x;

    for (int t = tid; t < IN_CH * 128; t += 512) {
        WsT[t] = WnT[t];
        DsT[t] = DT[t];
    }

    int o = tid & 127;
    int g = tid >> 7;     // 0..3 : points g*4 .. g*4+3

    u64t bP[3], bD[3];
#pragma unroll
    for (int c = 0; c < 3; c++) { bP[c] = 0ull; bD[c] = 0ull; }
    if (BIAS) {
#pragma unroll
        for (int c = 0; c < 3; c++) {
            float vp = biasP[b * 384 + o * 3 + c];
            float vd = biasD[b * 384 + o * 3 + c];
            bP[c] = pack2(vp, vp);
            bD[c] = pack2(vd, vd);
        }
    }
    __syncthreads();

#pragma unroll 1
    for (int t = 0; t < TPB; t++) {
        int blk = blk0 + t;

        const float4* inp4 = (const float4*)(in + (long)(b * BPB + blk) * IN_CH * 48);
        for (int tt = tid; tt < IN_CH * 12; tt += 512) ((float4*)xs)[tt] = inp4[tt];
        __syncthreads();

        u64t aP[3][2], aD[3][2];
#pragma unroll
        for (int c = 0; c < 3; c++) {
            aP[c][0] = bP[c]; aP[c][1] = bP[c];
            aD[c][0] = bD[c]; aD[c][1] = bD[c];
        }

#pragma unroll 2
        for (int i = 0; i < IN_CH; ++i) {
            float w  = WsT[i * 128 + o];
            float dd = DsT[i * 128 + o];
            u64t w2 = pack2(w, w);
            u64t d2 = pack2(dd, dd);
#pragma unroll
            for (int c = 0; c < 3; c++) {
                ulonglong2 X = *(const ulonglong2*)(xs + i * 48 + c * 16 + g * 4);
                aP[c][0] = fma2(w2, X.x, aP[c][0]);
                aP[c][1] = fma2(w2, X.y, aP[c][1]);
                aD[c][0] = fma2(d2, X.x, aD[c][0]);
                aD[c][1] = fma2(d2, X.y, aD[c][1]);
            }
        }

        float px[3][4], dx[3][4];
#pragma unroll
        for (int c = 0; c < 3; c++) {
            unpack2(aP[c][0], px[c][0], px[c][1]);
            unpack2(aP[c][1], px[c][2], px[c][3]);
            unpack2(aD[c][0], dx[c][0], dx[c][1]);
            unpack2(aD[c][1], dx[c][2], dx[c][3]);
        }

        float qv[3][4];
        float s0 = 0.f, s1 = 0.f, s2 = 0.f;
#pragma unroll
        for (int p = 0; p < 4; p++) {
            float q0 = px[0][p], q1 = px[1][p], q2 = px[2][p];
            float e0 = dx[0][p], e1 = dx[1][p], e2 = dx[2][p];
            float dot = q0 * e0 + q1 * e1 + q2 * e2;
            if (dot < 0.f) {
                float dns = e0 * e0 + e1 * e1 + e2 * e2;
                float tt2 = dot / (dns + EPSV);
                q0 -= tt2 * e0; q1 -= tt2 * e1; q2 -= tt2 * e2;
            }
            qv[0][p] = q0; qv[1][p] = q1; qv[2][p] = q2;
            s0 += q0; s1 += q1; s2 += q2;
        }
        if (STORE) {
            float4* out4 = (float4*)(out + ((long)(b * BPB + blk) * 128 + o) * 48);
#pragma unroll
            for (int c = 0; c < 3; c++)
                out4[c * 4 + g] = make_float4(qv[c][0], qv[c][1], qv[c][2], qv[c][3]);
        }

        red[tid * 3 + 0] = s0; red[tid * 3 + 1] = s1; red[tid * 3 + 2] = s2;
        __syncthreads();
        if (tid < 128) {
            float t0 = red[tid * 3 + 0] + red[(tid + 128) * 3 + 0]
                     + red[(tid + 256) * 3 + 0] + red[(tid + 384) * 3 + 0];
            float t1 = red[tid * 3 + 1] + red[(tid + 128) * 3 + 1]
                     + red[(tid + 256) * 3 + 1] + red[(tid + 384) * 3 + 1];
            float t2 = red[tid * 3 + 2] + red[(tid + 128) * 3 + 2]
                     + red[(tid + 256) * 3 + 2] + red[(tid + 384) * 3 + 2];
            float* dst = part + ((long)(b * BPB + blk)) * 384 + tid * 3;
            dst[0] = t0; dst[1] = t1; dst[2] = t2;
        }
        // next iteration's post-load sync orders red reads vs next writes
    }
}

// ---------------- bias from pooled mean ----------------
__global__ void __launch_bounds__(128)
bias_kernel(const float* __restrict__ part,
            const float* __restrict__ WnF,   // [128][256] normalized
            const float* __restrict__ Draw,  // [128][256] raw
            float* __restrict__ biasP, float* __restrict__ biasD) {
    __shared__ float mean[384];
    int b = blockIdx.x;
    int tid = threadIdx.x;  // 128
    for (int t = tid; t < 384; t += 128) {
        float s = 0.f;
#pragma unroll 8
        for (int blk = 0; blk < BPB; blk++) s += part[((long)(b * BPB + blk)) * 384 + t];
        mean[t] = s * (1.f / (float)NPTS);
    }
    __syncthreads();
    int o = tid;
    float p0 = 0.f, p1 = 0.f, p2 = 0.f, d0 = 0.f, d1 = 0.f, d2 = 0.f;
#pragma unroll 4
    for (int i = 0; i < 128; i++) {
        float w  = WnF[o * 256 + 128 + i];
        float dd = Draw[o * 256 + 128 + i];
        float m0 = mean[i * 3 + 0], m1 = mean[i * 3 + 1], m2 = mean[i * 3 + 2];
        p0 += w * m0;  p1 += w * m1;  p2 += w * m2;
        d0 += dd * m0; d1 += dd * m1; d2 += dd * m2;
    }
    biasP[b * 384 + o * 3 + 0] = p0;
    biasP[b * 384 + o * 3 + 1] = p1;
    biasP[b * 384 + o * 3 + 2] = p2;
    biasD[b * 384 + o * 3 + 0] = d0;
    biasD[b * 384 + o * 3 + 1] = d1;
    biasD[b * 384 + o * 3 + 2] = d2;
}

// ---------------- final mean over N -> output [B,384] ----------------
__global__ void __launch_bounds__(384)
final_kernel(const float* __restrict__ part, float* __restrict__ outp) {
    int b = blockIdx.x;
    int t = threadIdx.x;  // 384
    float s = 0.f;
#pragma unroll 8
    for (int blk = 0; blk < BPB; blk++) s += part[((long)(b * BPB + blk)) * 384 + t];
    outp[b * 384 + t] = s * (1.f / (float)NPTS);
}

// ---------------- launch ----------------
extern "C" void kernel_launch(void* const* d_in, const int* in_sizes, int n_in,
                              void* d_out, int out_size) {
    const float* pc   = (const float*)d_in[0];
    const float* Wpos = (const float*)d_in[1];
    const float* Dpos = (const float*)d_in[2];
    const float* W1   = (const float*)d_in[3];
    const float* D1   = (const float*)d_in[4];
    const float* W2   = (const float*)d_in[5];
    const float* D2   = (const float*)d_in[6];
    const float* W3   = (const float*)d_in[7];
    const float* D3   = (const float*)d_in[8];
    float* outp = (float*)d_out;

    int smem1 = (64 * 128 * 2) * 4 + 64 * 48 * 4 + 512 * 3 * 4;    //  83968 B
    int smem2 = (128 * 128 * 2) * 4 + 128 * 48 * 4 + 512 * 3 * 4;  // 161792 B
    cudaFuncSetAttribute(layer_kernel<64, true, false>,
                         cudaFuncAttributeMaxDynamicSharedMemorySize, smem1);
    cudaFuncSetAttribute(layer_kernel<128, true, true>,
                         cudaFuncAttributeMaxDynamicSharedMemorySize, smem2);
    cudaFuncSetAttribute(layer_kernel<128, false, true>,
                         cudaFuncAttributeMaxDynamicSharedMemorySize, smem2);

    void *net0p, *net1p, *net2p;
    void *wn1t, *d1t, *wn2t, *d2t, *wn3t, *d3t, *wn2f, *wn3f;
    void *part1, *part2, *part3, *bp2, *bd2, *bp3, *bd3;
    cudaGetSymbolAddress(&net0p, g_net0);
    cudaGetSymbolAddress(&net1p, g_net1);
    cudaGetSymbolAddress(&net2p, g_net2);
    cudaGetSymbolAddress(&wn1t, g_Wn1T);
    cudaGetSymbolAddress(&d1t,  g_D1T);
    cudaGetSymbolAddress(&wn2t, g_Wn2T);
    cudaGetSymbolAddress(&d2t,  g_D2T);
    cudaGetSymbolAddress(&wn3t, g_Wn3T);
    cudaGetSymbolAddress(&d3t,  g_D3T);
    cudaGetSymbolAddress(&wn2f, g_Wn2F);
    cudaGetSymbolAddress(&wn3f, g_Wn3F);
    cudaGetSymbolAddress(&part1, g_part1);
    cudaGetSymbolAddress(&part2, g_part2);
    cudaGetSymbolAddress(&part3, g_part3);
    cudaGetSymbolAddress(&bp2, g_biasP2);
    cudaGetSymbolAddress(&bd2, g_biasD2);
    cudaGetSymbolAddress(&bp3, g_biasP3);
    cudaGetSymbolAddress(&bd3, g_biasD3);

    prep_norm_kernel<<<385, 128>>>(Wpos, W1, W2, W3);
    prep_transpose_kernel<<<160, 256>>>(D1, D2, D3);
    knn_kernel<<<dim3(NPTS / 8, NB), 256>>>(pc);
    edge_pos_kernel<<<NB * NPTS / 2, 128>>>(pc, Dpos);

    layer_kernel<64, true, false><<<NB * LBPB, 512, smem1>>>(
        (const float*)net0p, (const float*)wn1t, (const float*)d1t,
        nullptr, nullptr, (float*)net1p, (float*)part1);

    bias_kernel<<<NB, 128>>>((const float*)part1, (const float*)wn2f, D2,
                             (float*)bp2, (float*)bd2);

    layer_kernel<128, true, true><<<NB * LBPB, 512, smem2>>>(
        (const float*)net1p, (const float*)wn2t, (const float*)d2t,
        (const float*)bp2, (const float*)bd2, (float*)net2p, (float*)part2);

    bias_kernel<<<NB, 128>>>((const float*)part2, (const float*)wn3f, D3,
                             (float*)bp3, (float*)bd3);

    layer_kernel<128, false, true><<<NB * LBPB, 512, smem2>>>(
        (const float*)net2p, (const float*)wn3t, (const float*)d3t,
        (const float*)bp3, (const float*)bd3, nullptr, (float*)part3);

    final_kernel<<<NB, 384>>>((const float*)part3, outp);
}